// round 1
// baseline (speedup 1.0000x reference)
#include <cuda_runtime.h>
#include <cstdint>

// out[b,i,h,p] = sum_{l,kh,kw} W[l,kh,kw,i] * A(b,l,kh,kw,h,p)
// A = valid(p+kw) * ( X[b,256+l, ((h+6)%7)+kh-1, w] + X[b,l, h+kh-1, w] ),
//     w = (p+kw+5)%7, valid when 1 <= p+kw <= 7, zero-pad on row OOB.
// GEMM: M = B*49, N = 512, K = 256*3*3 = 2304.

#define THREADS 256
#define KB      64          // K-chunk
#define NPOS    49          // 7*7 output positions per batch
#define ROWP    52          // padded As row (pairs of f32, 8B aligned)
#define K_TOT   2304
#define C_IN    512
#define HW      49
#define XS_ELEMS (C_IN * HW)   // 25088 floats = 100352 B

__global__ void __launch_bounds__(THREADS, 1)
shiftconv_fma2_kernel(const float* __restrict__ x,
                      const float* __restrict__ Wg,
                      float* __restrict__ out, int Bn)
{
    extern __shared__ float smem[];
    float* Xs = smem;                 // [512][7][7]
    float* As = smem + XS_ELEMS;      // [KB][ROWP]

    const int b   = blockIdx.x;
    const int tid = threadIdx.x;
    if (b >= Bn) return;

    // ---- stage x[b] into shared (coalesced float4) ----
    {
        const float4* xg  = reinterpret_cast<const float4*>(x + (size_t)b * XS_ELEMS);
        float4*       xs4 = reinterpret_cast<float4*>(Xs);
        for (int idx = tid; idx < XS_ELEMS / 4; idx += THREADS) xs4[idx] = xg[idx];
    }

    // each thread owns 2 output channels: tid and tid+256
    unsigned long long acc0[ROWP / 2];
    unsigned long long acc1[ROWP / 2];
#pragma unroll
    for (int j = 0; j < ROWP / 2; j++) { acc0[j] = 0ull; acc1[j] = 0ull; }

    for (int k0 = 0; k0 < K_TOT; k0 += KB) {
        __syncthreads();   // protect As reuse (and Xs on first iter)

        // ---- build gathered A tile: As[kk][j], j = h*7+p ----
        for (int idx = tid; idx < KB * ROWP; idx += THREADS) {
            int kk = idx / ROWP;
            int j  = idx - kk * ROWP;
            float v = 0.f;
            if (j < NPOS) {
                int h  = j / 7;
                int p  = j - h * 7;
                int k  = k0 + kk;
                int l  = k / 9;
                int r9 = k - l * 9;
                int kh = r9 / 3;
                int kw = r9 - kh * 3;
                int q  = p + kw - 1;              // unfolded w-position (pre-roll)
                if ((unsigned)q <= 6u) {
                    int w  = q - 1; if (w < 0) w = 6;   // (p+kw+5)%7
                    int r0 = h + kh - 1;                 // group-0 row
                    int r1 = ((h + 6) % 7) + kh - 1;     // group-1 row (rolled h)
                    if ((unsigned)r0 <= 6u) v += Xs[l * HW + r0 * 7 + w];
                    if ((unsigned)r1 <= 6u) v += Xs[(256 + l) * HW + r1 * 7 + w];
                }
            }
            As[idx] = v;
        }
        __syncthreads();

        // ---- FFMA2 accumulation: 2 cols/thread, 26 pairs of positions ----
        const float* wbase = Wg + (size_t)k0 * 512 + tid;
#pragma unroll 4
        for (int kk = 0; kk < KB; kk++) {
            float w0 = __ldg(wbase + (size_t)kk * 512);
            float w1 = __ldg(wbase + (size_t)kk * 512 + 256);
            unsigned long long wd0, wd1;
            asm("mov.b64 %0, {%1, %1};" : "=l"(wd0) : "f"(w0));
            asm("mov.b64 %0, {%1, %1};" : "=l"(wd1) : "f"(w1));
            const unsigned long long* arow =
                reinterpret_cast<const unsigned long long*>(As + kk * ROWP);
#pragma unroll
            for (int jp = 0; jp < ROWP / 2; jp++) {
                unsigned long long a = arow[jp];     // broadcast LDS.64
                asm("fma.rn.f32x2 %0, %1, %2, %0;" : "+l"(acc0[jp]) : "l"(a), "l"(wd0));
                asm("fma.rn.f32x2 %0, %1, %2, %0;" : "+l"(acc1[jp]) : "l"(a), "l"(wd1));
            }
        }
    }

    // ---- epilogue: out[b][i][h][p], i stride 49 ----
    float* op0 = out + (size_t)b * XS_ELEMS + (size_t)tid * HW;
    float* op1 = op0 + (size_t)256 * HW;
#pragma unroll
    for (int jp = 0; jp < ROWP / 2; jp++) {
        float lo0, hi0, lo1, hi1;
        asm("mov.b64 {%0, %1}, %2;" : "=f"(lo0), "=f"(hi0) : "l"(acc0[jp]));
        asm("mov.b64 {%0, %1}, %2;" : "=f"(lo1), "=f"(hi1) : "l"(acc1[jp]));
        int j = 2 * jp;
        if (j < NPOS)     { op0[j]     = lo0; op1[j]     = lo1; }
        if (j + 1 < NPOS) { op0[j + 1] = hi0; op1[j + 1] = hi1; }
    }
}

extern "C" void kernel_launch(void* const* d_in, const int* in_sizes, int n_in,
                              void* d_out, int out_size)
{
    const float* x = (const float*)d_in[0];
    const float* W = (const float*)d_in[1];
    int xs = in_sizes[0];
    // defensive: detect swapped input order (W has 1,179,648 elements)
    if (n_in >= 2 && xs == 256 * 3 * 3 * 512) {
        x = (const float*)d_in[1];
        W = (const float*)d_in[0];
        xs = in_sizes[1];
    }
    int Bn = xs / XS_ELEMS;   // 1024

    const int SMEM = (XS_ELEMS + KB * ROWP) * (int)sizeof(float);  // 113664 B
    cudaFuncSetAttribute(shiftconv_fma2_kernel,
                         cudaFuncAttributeMaxDynamicSharedMemorySize, SMEM);
    shiftconv_fma2_kernel<<<Bn, THREADS, SMEM>>>(x, W, (float*)d_out, Bn);
}

// round 6
// speedup vs baseline: 2.1559x; 2.1559x over previous
#include <cuda_runtime.h>
#include <cuda_bf16.h>
#include <cstdint>

#define B_N     1024
#define HW      49
#define XS      25088      // 512*49
#define K_TOT   2304
#define NOUT    512
#define M_TOT   50176
#define SLOTS   78         // 56 main (r*7+q) + 21 special (kh*7+q) + 1 zero
#define MT      128
#define NT      128
#define KC      32
#define NCHUNK  72         // 2304/32

// row stride in smem tiles: 64B data + 16B pad (conflict-free ldmatrix)
#define RS      80
#define TS      (128 * RS)          // 10240 B per tile
#define BUFS    (4 * TS)            // Ahi,Alo,Bhi,Blo
#define SMEM_GEMM (2 * BUFS)        // 81920 B (double buffered)

// ---------------- global scratch ----------------
__device__ __nv_bfloat16 g_Ahi[B_N * SLOTS * 256];   // [b][slot][l]
__device__ __nv_bfloat16 g_Alo[B_N * SLOTS * 256];
__device__ __nv_bfloat16 g_Bhi[NOUT * K_TOT];        // [i][tap*256+l]
__device__ __nv_bfloat16 g_Blo[NOUT * K_TOT];

// ---------------- precompute: W split + permute ----------------
__global__ void wsplit_kernel(const float* __restrict__ W) {
    int idx = blockIdx.x * blockDim.x + threadIdx.x;
    if (idx >= NOUT * K_TOT) return;
    int i = idx / K_TOT, kk = idx - i * K_TOT;
    int tap = kk >> 8, l = kk & 255;
    float v = W[(size_t)(l * 9 + tap) * 512 + i];     // W[l][kh][kw][i]
    __nv_bfloat16 hi = __float2bfloat16(v);
    g_Bhi[idx] = hi;
    g_Blo[idx] = __float2bfloat16(v - __bfloat162float(hi));
}

// ---------------- precompute: shifted-sum image ----------------
// main slot (r,q), r in [0,7]:  M[r] = [r<=6]X0[r,w] + [r>=1]X1[r-1,w], w=(q+6)%7
// special (kh,q) for h==0 rows; slot 77 = zero
__global__ void mbuild_kernel(const float* __restrict__ x) {
    extern __shared__ float Xs[];
    int b = blockIdx.x, tid = threadIdx.x;
    const float4* xg = (const float4*)(x + (size_t)b * XS);
    float4* xs4 = (float4*)Xs;
    for (int i = tid; i < XS / 4; i += 256) xs4[i] = xg[i];
    __syncthreads();
    for (int idx = tid; idx < SLOTS * 256; idx += 256) {
        int slot = idx >> 8, l = idx & 255;
        float v = 0.f;
        if (slot < 56) {
            int r = slot / 7, q = slot - r * 7;
            int w = (q == 0) ? 6 : q - 1;
            if (r <= 6) v += Xs[l * 49 + r * 7 + w];
            if (r >= 1) v += Xs[(256 + l) * 49 + (r - 1) * 7 + w];
        } else if (slot < 77) {
            int s = slot - 56;
            int kh = s / 7, q = s - kh * 7;
            int w = (q == 0) ? 6 : q - 1;
            if (kh == 0)      v = Xs[(256 + l) * 49 + 35 + w];
            else if (kh == 1) v = Xs[l * 49 + w] + Xs[(256 + l) * 49 + 42 + w];
            else              v = Xs[l * 49 + 7 + w];
        }
        __nv_bfloat16 hi = __float2bfloat16(v);
        size_t o = (size_t)b * (SLOTS * 256) + idx;
        g_Ahi[o] = hi;
        g_Alo[o] = __float2bfloat16(v - __bfloat162float(hi));
    }
}

// ---------------- PTX helpers ----------------
__device__ __forceinline__ uint32_t smem_u32(const void* p) {
    uint32_t a;
    asm("{ .reg .u64 t; cvta.to.shared.u64 t, %1; cvt.u32.u64 %0, t; }" : "=r"(a) : "l"(p));
    return a;
}
__device__ __forceinline__ void ldm4(uint32_t* r, uint32_t addr) {
    asm volatile("ldmatrix.sync.aligned.m8n8.x4.shared.b16 {%0,%1,%2,%3}, [%4];"
        : "=r"(r[0]), "=r"(r[1]), "=r"(r[2]), "=r"(r[3]) : "r"(addr));
}
__device__ __forceinline__ void mma_bf16(float* d, const uint32_t* a, uint32_t b0, uint32_t b1) {
    asm volatile("mma.sync.aligned.m16n8k16.row.col.f32.bf16.bf16.f32 "
        "{%0,%1,%2,%3}, {%4,%5,%6,%7}, {%8,%9}, {%0,%1,%2,%3};"
        : "+f"(d[0]), "+f"(d[1]), "+f"(d[2]), "+f"(d[3])
        : "r"(a[0]), "r"(a[1]), "r"(a[2]), "r"(a[3]), "r"(b0), "r"(b1));
}
#define CP16(dst, src) asm volatile("cp.async.cg.shared.global [%0], [%1], 16;" :: "r"(dst), "l"(src))
#define CP_COMMIT()    asm volatile("cp.async.commit_group;" ::: "memory")
#define CP_WAIT(n)     asm volatile("cp.async.wait_group %0;" :: "n"(n) : "memory")

// ---------------- chunk loader: A via slot lookup, B direct ----------------
__device__ __forceinline__ void load_chunk(int c, int buf, uint32_t sb,
                                           int m0, int n0, int tid) {
    int tap = c >> 3, l0 = (c & 7) << 5;
    int r2 = tid >> 1, half = tid & 1;
    // A row -> slot
    int m = m0 + r2;
    int b = m / 49, j = m - b * 49;
    int h = j / 7, p = j - h * 7;
    int kh = tap / 3, kw = tap - kh * 3;
    int q = p + kw - 1;
    int slot;
    if ((unsigned)q > 6u)      slot = 77;
    else if (h >= 1)           slot = (h + kh - 1) * 7 + q;
    else                       slot = 56 + kh * 7 + q;
    const __nv_bfloat16* srcA = (half ? g_Alo : g_Ahi) +
                                ((size_t)b * SLOTS + slot) * 256 + l0;
    uint32_t dstA = sb + buf * BUFS + half * TS + r2 * RS;
    CP16(dstA,      srcA);
    CP16(dstA + 16, srcA + 8);
    CP16(dstA + 32, srcA + 16);
    CP16(dstA + 48, srcA + 24);
    const __nv_bfloat16* srcB = (half ? g_Blo : g_Bhi) +
                                (size_t)(n0 + r2) * K_TOT + tap * 256 + l0;
    uint32_t dstB = sb + buf * BUFS + 2 * TS + half * TS + r2 * RS;
    CP16(dstB,      srcB);
    CP16(dstB + 16, srcB + 8);
    CP16(dstB + 32, srcB + 16);
    CP16(dstB + 48, srcB + 24);
}

// ---------------- main GEMM: M=50176, N=512, K=2304, bf16 3-term split ----------------
__global__ void __launch_bounds__(256, 2)
gemm_kernel(float* __restrict__ out)
{
    extern __shared__ char smem[];
    const uint32_t sb = smem_u32(smem);
    const int tid = threadIdx.x, lane = tid & 31, wid = tid >> 5;
    const int wm = wid >> 2, wn = wid & 3;              // warp grid 2(M) x 4(N)
    const int n0 = blockIdx.x * NT, m0 = blockIdx.y * MT;

    float acc[4][4][4];
#pragma unroll
    for (int a = 0; a < 4; a++)
#pragma unroll
        for (int b = 0; b < 4; b++)
#pragma unroll
            for (int d = 0; d < 4; d++) acc[a][b][d] = 0.f;

    load_chunk(0, 0, sb, m0, n0, tid);
    CP_COMMIT();

    const int lr = (lane & 7) + ((lane >> 3) & 1) * 8;  // row within 16
    const int lc = ((lane >> 4) & 1) * 16;              // 0 / 16 byte col

    for (int c = 0; c < NCHUNK; c++) {
        int buf = c & 1;
        if (c + 1 < NCHUNK) {
            load_chunk(c + 1, buf ^ 1, sb, m0, n0, tid);
            CP_COMMIT();
            CP_WAIT(1);
        } else {
            CP_WAIT(0);
        }
        __syncthreads();

        uint32_t aHb = sb + buf * BUFS;
        uint32_t aLb = aHb + TS;
        uint32_t bHb = aHb + 2 * TS;
        uint32_t bLb = aHb + 3 * TS;

#pragma unroll
        for (int s = 0; s < 2; s++) {                   // k-steps of 16
            uint32_t bh[8], bl[8];
#pragma unroll
            for (int pr = 0; pr < 2; pr++) {
                uint32_t ba = (uint32_t)(wn * 32 + pr * 16 + lr) * RS + s * 32 + lc;
                ldm4(bh + pr * 4, bHb + ba);
                ldm4(bl + pr * 4, bLb + ba);
            }
#pragma unroll
            for (int ms = 0; ms < 4; ms++) {
                uint32_t aa = (uint32_t)(wm * 64 + ms * 16 + lr) * RS + s * 32 + lc;
                uint32_t ah[4], al[4];
                ldm4(ah, aHb + aa);
                ldm4(al, aLb + aa);
#pragma unroll
                for (int n = 0; n < 4; n++) {
                    int pr = n >> 1, t = n & 1;
                    uint32_t b0h = bh[pr * 4 + t], b1h = bh[pr * 4 + t + 2];
                    uint32_t b0l = bl[pr * 4 + t], b1l = bl[pr * 4 + t + 2];
                    mma_bf16(acc[ms][n], ah, b0h, b1h);   // hi*hi
                    mma_bf16(acc[ms][n], ah, b0l, b1l);   // hi*lo
                    mma_bf16(acc[ms][n], al, b0h, b1h);   // lo*hi
                }
            }
        }
        __syncthreads();
    }

    // ---- epilogue: transpose through smem, coalesced stores ----
    float* sD = (float*)smem;                            // [128 i][132 m]
#pragma unroll
    for (int ms = 0; ms < 4; ms++)
#pragma unroll
        for (int n = 0; n < 4; n++) {
            int m = wm * 64 + ms * 16 + (lane >> 2);
            int i = wn * 32 + n * 8 + (lane & 3) * 2;
            sD[i * 132 + m]           = acc[ms][n][0];
            sD[(i + 1) * 132 + m]     = acc[ms][n][1];
            sD[i * 132 + m + 8]       = acc[ms][n][2];
            sD[(i + 1) * 132 + m + 8] = acc[ms][n][3];
        }
    __syncthreads();
    for (int idx = tid; idx < 128 * 128; idx += 256) {
        int i = idx >> 7, mm = idx & 127;
        int m = m0 + mm;
        int b = m / 49, j = m - b * 49;
        out[(size_t)b * XS + (size_t)(n0 + i) * HW + j] = sD[i * 132 + mm];
    }
}

// ---------------- launch ----------------
extern "C" void kernel_launch(void* const* d_in, const int* in_sizes, int n_in,
                              void* d_out, int out_size)
{
    const float* x = (const float*)d_in[0];
    const float* W = (const float*)d_in[1];
    if (n_in >= 2 && in_sizes[0] == 256 * 3 * 3 * 512) {   // defensive swap
        x = (const float*)d_in[1];
        W = (const float*)d_in[0];
    }

    cudaFuncSetAttribute(mbuild_kernel,
                         cudaFuncAttributeMaxDynamicSharedMemorySize, XS * 4);
    cudaFuncSetAttribute(gemm_kernel,
                         cudaFuncAttributeMaxDynamicSharedMemorySize, SMEM_GEMM);

    wsplit_kernel<<<(NOUT * K_TOT + 255) / 256, 256>>>(W);
    mbuild_kernel<<<B_N, 256, XS * 4>>>(x);
    gemm_kernel<<<dim3(NOUT / NT, M_TOT / MT), 256, SMEM_GEMM>>>((float*)d_out);
}

// round 9
// speedup vs baseline: 2.2153x; 1.0276x over previous
#include <cuda_runtime.h>
#include <cuda_bf16.h>
#include <cstdint>

#define B_N     1024
#define HW      49
#define XS      25088      // 512*49
#define K_TOT   2304
#define NOUT    512
#define M_TOT   50176
#define SLOTS   78         // 56 main (r*7+q) + 21 special (kh*7+q) + 1 zero
#define MT      128
#define NT      128
#define KC      32
#define NCHUNK  72         // 2304/32

// row stride in smem tiles: 64B data + 16B pad (conflict-free ldmatrix & STS)
#define RS      80
#define TS      (128 * RS)          // 10240 B per tile
#define BUFS    (4 * TS)            // Ahi,Alo,Bhi,Blo
#define SMEM_GEMM (2 * BUFS)        // 81920 B (double buffered)

// ---------------- global scratch ----------------
__device__ __nv_bfloat16 g_Ahi[B_N * SLOTS * 256];   // [b][slot][l]
__device__ __nv_bfloat16 g_Alo[B_N * SLOTS * 256];
__device__ __nv_bfloat16 g_Bhi[NOUT * K_TOT];        // [i][tap*256+l]
__device__ __nv_bfloat16 g_Blo[NOUT * K_TOT];

// ---------------- precompute: W split + permute ----------------
__global__ void wsplit_kernel(const float* __restrict__ W) {
    int idx = blockIdx.x * blockDim.x + threadIdx.x;
    if (idx >= NOUT * K_TOT) return;
    int i = idx / K_TOT, kk = idx - i * K_TOT;
    int tap = kk >> 8, l = kk & 255;
    float v = W[(size_t)(l * 9 + tap) * 512 + i];     // W[l][kh][kw][i]
    __nv_bfloat16 hi = __float2bfloat16(v);
    g_Bhi[idx] = hi;
    g_Blo[idx] = __float2bfloat16(v - __bfloat162float(hi));
}

// ---------------- precompute: shifted-sum image ----------------
__global__ void mbuild_kernel(const float* __restrict__ x) {
    extern __shared__ float Xs[];
    int b = blockIdx.x, tid = threadIdx.x;
    const float4* xg = (const float4*)(x + (size_t)b * XS);
    float4* xs4 = (float4*)Xs;
    for (int i = tid; i < XS / 4; i += 256) xs4[i] = xg[i];
    __syncthreads();
    for (int idx = tid; idx < SLOTS * 256; idx += 256) {
        int slot = idx >> 8, l = idx & 255;
        float v = 0.f;
        if (slot < 56) {
            int r = slot / 7, q = slot - r * 7;
            int w = (q == 0) ? 6 : q - 1;
            if (r <= 6) v += Xs[l * 49 + r * 7 + w];
            if (r >= 1) v += Xs[(256 + l) * 49 + (r - 1) * 7 + w];
        } else if (slot < 77) {
            int s = slot - 56;
            int kh = s / 7, q = s - kh * 7;
            int w = (q == 0) ? 6 : q - 1;
            if (kh == 0)      v = Xs[(256 + l) * 49 + 35 + w];
            else if (kh == 1) v = Xs[l * 49 + w] + Xs[(256 + l) * 49 + 42 + w];
            else              v = Xs[l * 49 + 7 + w];
        }
        __nv_bfloat16 hi = __float2bfloat16(v);
        size_t o = (size_t)b * (SLOTS * 256) + idx;
        g_Ahi[o] = hi;
        g_Alo[o] = __float2bfloat16(v - __bfloat162float(hi));
    }
}

// ---------------- PTX helpers ----------------
__device__ __forceinline__ uint32_t smem_u32(const void* p) {
    uint32_t a;
    asm("{ .reg .u64 t; cvta.to.shared.u64 t, %1; cvt.u32.u64 %0, t; }" : "=r"(a) : "l"(p));
    return a;
}
__device__ __forceinline__ void ldm4(uint32_t* r, uint32_t addr) {
    asm volatile("ldmatrix.sync.aligned.m8n8.x4.shared.b16 {%0,%1,%2,%3}, [%4];"
        : "=r"(r[0]), "=r"(r[1]), "=r"(r[2]), "=r"(r[3]) : "r"(addr));
}
__device__ __forceinline__ void mma_bf16(float* d, const uint32_t* a, uint32_t b0, uint32_t b1) {
    asm volatile("mma.sync.aligned.m16n8k16.row.col.f32.bf16.bf16.f32 "
        "{%0,%1,%2,%3}, {%4,%5,%6,%7}, {%8,%9}, {%0,%1,%2,%3};"
        : "+f"(d[0]), "+f"(d[1]), "+f"(d[2]), "+f"(d[3])
        : "r"(a[0]), "r"(a[1]), "r"(a[2]), "r"(a[3]), "r"(b0), "r"(b1));
}
#define CP16(dst, src) asm volatile("cp.async.cg.shared.global [%0], [%1], 16;" :: "r"(dst), "l"(src))
#define CP_COMMIT()    asm volatile("cp.async.commit_group;" ::: "memory")
#define CP_WAIT(n)     asm volatile("cp.async.wait_group %0;" :: "n"(n) : "memory")

// ---------------- chunk loader: conflict-free lane mapping ----------------
// half = tid>>7 (hi/lo), r = tid&127 (row). Each warp's 32 lanes hit 32
// consecutive rows at stride 80B -> bank-group perm (5r mod 8), no conflicts.
__device__ __forceinline__ void load_chunk(int c, int buf, uint32_t sb,
                                           int m0, int n0, int tid) {
    int tap = c >> 3, l0 = (c & 7) << 5;
    int half = tid >> 7, r = tid & 127;
    // ---- A row r -> slot ----
    int m = m0 + r;
    int b = m / 49, j = m - b * 49;
    int h = j / 7, p = j - h * 7;
    int kh = tap / 3, kw = tap - kh * 3;
    int q = p + kw - 1;
    int slot;
    if ((unsigned)q > 6u)      slot = 77;
    else if (h >= 1)           slot = (h + kh - 1) * 7 + q;
    else                       slot = 56 + kh * 7 + q;
    const __nv_bfloat16* srcA = (half ? g_Alo : g_Ahi) +
                                ((size_t)b * SLOTS + slot) * 256 + l0;
    uint32_t dstA = sb + buf * BUFS + half * TS + r * RS;
    CP16(dstA,      srcA);
    CP16(dstA + 16, srcA + 8);
    CP16(dstA + 32, srcA + 16);
    CP16(dstA + 48, srcA + 24);
    // ---- B row r ----
    const __nv_bfloat16* srcB = (half ? g_Blo : g_Bhi) +
                                (size_t)(n0 + r) * K_TOT + tap * 256 + l0;
    uint32_t dstB = sb + buf * BUFS + (2 + half) * TS + r * RS;
    CP16(dstB,      srcB);
    CP16(dstB + 16, srcB + 8);
    CP16(dstB + 32, srcB + 16);
    CP16(dstB + 48, srcB + 24);
}

// ---------------- main GEMM: M=50176, N=512, K=2304, bf16 3-term split ----------------
__global__ void __launch_bounds__(256, 2)
gemm_kernel(float* __restrict__ out)
{
    extern __shared__ char smem[];
    const uint32_t sb = smem_u32(smem);
    const int tid = threadIdx.x, lane = tid & 31, wid = tid >> 5;
    const int wm = wid >> 2, wn = wid & 3;              // warp grid 2(M) x 4(N)
    const int n0 = blockIdx.x * NT, m0 = blockIdx.y * MT;

    float acc[4][4][4];
#pragma unroll
    for (int a = 0; a < 4; a++)
#pragma unroll
        for (int b = 0; b < 4; b++)
#pragma unroll
            for (int d = 0; d < 4; d++) acc[a][b][d] = 0.f;

    // prologue: stage 0
    load_chunk(0, 0, sb, m0, n0, tid);
    CP_COMMIT();

    const int lr = (lane & 7) + ((lane >> 3) & 1) * 8;  // row within 16
    const int lc = ((lane >> 4) & 1) * 16;              // 0 / 16 byte col

    for (int c = 0; c < NCHUNK; c++) {
        int buf = c & 1;
        CP_WAIT(0);          // chunk c landed
        __syncthreads();     // all warps done with buffer buf^1 (iter c-1)
        if (c + 1 < NCHUNK) {
            load_chunk(c + 1, buf ^ 1, sb, m0, n0, tid);   // overlaps compute(c)
            CP_COMMIT();
        }

        uint32_t aHb = sb + buf * BUFS;
        uint32_t aLb = aHb + TS;
        uint32_t bHb = aHb + 2 * TS;
        uint32_t bLb = aHb + 3 * TS;

#pragma unroll
        for (int s = 0; s < 2; s++) {                   // k-steps of 16
            uint32_t bh[8], bl[8];
#pragma unroll
            for (int pr = 0; pr < 2; pr++) {
                uint32_t ba = (uint32_t)(wn * 32 + pr * 16 + lr) * RS + s * 32 + lc;
                ldm4(bh + pr * 4, bHb + ba);
                ldm4(bl + pr * 4, bLb + ba);
            }
#pragma unroll
            for (int ms = 0; ms < 4; ms++) {
                uint32_t aa = (uint32_t)(wm * 64 + ms * 16 + lr) * RS + s * 32 + lc;
                uint32_t ah[4], al[4];
                ldm4(ah, aHb + aa);
                ldm4(al, aLb + aa);
                // term-major: 4 independent accs between same-acc RAWs
#pragma unroll
                for (int n = 0; n < 4; n++) {
                    int pr = n >> 1, t = n & 1;
                    mma_bf16(acc[ms][n], ah, bh[pr * 4 + t], bh[pr * 4 + t + 2]);
                }
#pragma unroll
                for (int n = 0; n < 4; n++) {
                    int pr = n >> 1, t = n & 1;
                    mma_bf16(acc[ms][n], ah, bl[pr * 4 + t], bl[pr * 4 + t + 2]);
                }
#pragma unroll
                for (int n = 0; n < 4; n++) {
                    int pr = n >> 1, t = n & 1;
                    mma_bf16(acc[ms][n], al, bh[pr * 4 + t], bh[pr * 4 + t + 2]);
                }
            }
        }
    }
    __syncthreads();

    // ---- epilogue: transpose through smem, coalesced stores ----
    float* sD = (float*)smem;                            // [128 i][132 m]
#pragma unroll
    for (int ms = 0; ms < 4; ms++)
#pragma unroll
        for (int n = 0; n < 4; n++) {
            int m = wm * 64 + ms * 16 + (lane >> 2);
            int i = wn * 32 + n * 8 + (lane & 3) * 2;
            sD[i * 132 + m]           = acc[ms][n][0];
            sD[(i + 1) * 132 + m]     = acc[ms][n][1];
            sD[i * 132 + m + 8]       = acc[ms][n][2];
            sD[(i + 1) * 132 + m + 8] = acc[ms][n][3];
        }
    __syncthreads();
    for (int idx = tid; idx < 128 * 128; idx += 256) {
        int i = idx >> 7, mm = idx & 127;
        int m = m0 + mm;
        int b = m / 49, j = m - b * 49;
        out[(size_t)b * XS + (size_t)(n0 + i) * HW + j] = sD[i * 132 + mm];
    }
}

// ---------------- launch ----------------
extern "C" void kernel_launch(void* const* d_in, const int* in_sizes, int n_in,
                              void* d_out, int out_size)
{
    const float* x = (const float*)d_in[0];
    const float* W = (const float*)d_in[1];
    if (n_in >= 2 && in_sizes[0] == 256 * 3 * 3 * 512) {   // defensive swap
        x = (const float*)d_in[1];
        W = (const float*)d_in[0];
    }

    cudaFuncSetAttribute(mbuild_kernel,
                         cudaFuncAttributeMaxDynamicSharedMemorySize, XS * 4);
    cudaFuncSetAttribute(gemm_kernel,
                         cudaFuncAttributeMaxDynamicSharedMemorySize, SMEM_GEMM);

    wsplit_kernel<<<(NOUT * K_TOT + 255) / 256, 256>>>(W);
    mbuild_kernel<<<B_N, 256, XS * 4>>>(x);
    gemm_kernel<<<dim3(NOUT / NT, M_TOT / MT), 256, SMEM_GEMM>>>((float*)d_out);
}